// round 2
// baseline (speedup 1.0000x reference)
#include <cuda_runtime.h>

#define NN 50000
#define NE 800000
#define DD 128
#define BM 64
#define SCAN_T 1024
#define CHUNK 49   // ceil(NN / SCAN_T)

// Scratch (__device__ globals per allocation rules)
__device__ float g_h[NN * DD];        // projected node features
__device__ float g_degs[NN];          // in-degree + 1
__device__ float g_norm[NN];          // degs^-0.5
__device__ float g_Wt[DD * DD];       // W transposed
__device__ int   g_cnt[NN];           // in-degree histogram
__device__ int   g_rowptr[NN + 1];    // CSR row pointers
__device__ int   g_cursor[NN];        // scatter cursors
__device__ int2  g_edata[NE];         // packed (src, etype) sorted by dst

// Zero histogram + transpose W, one launch
__global__ void k_pre(const float* __restrict__ W) {
    int i = blockIdx.x * blockDim.x + threadIdx.x;
    if (i < NN) g_cnt[i] = 0;
    if (i < DD * DD) {
        int d = i >> 7, k = i & 127;
        g_Wt[k * DD + d] = W[i];
    }
}

__global__ void k_count(const int* __restrict__ dst) {
    int e = blockIdx.x * blockDim.x + threadIdx.x;
    if (e < NE) atomicAdd(&g_cnt[dst[e]], 1);
}

// Single-block scan: rowptr/cursor = exclusive prefix of cnt; also degs & norm.
__global__ void k_scan() {
    __shared__ int sp[SCAN_T];
    int t = threadIdx.x;
    int base = t * CHUNK;
    int s = 0;
    #pragma unroll
    for (int i = 0; i < CHUNK; i++) {
        int idx = base + i;
        if (idx < NN) s += g_cnt[idx];
    }
    sp[t] = s;
    __syncthreads();
    for (int off = 1; off < SCAN_T; off <<= 1) {
        int v = (t >= off) ? sp[t - off] : 0;
        __syncthreads();
        sp[t] += v;
        __syncthreads();
    }
    int run = sp[t] - s;   // exclusive prefix at chunk start
    #pragma unroll
    for (int i = 0; i < CHUNK; i++) {
        int idx = base + i;
        if (idx < NN) {
            int c = g_cnt[idx];
            g_rowptr[idx] = run;
            g_cursor[idx] = run;
            run += c;
            float dg = (float)c + 1.0f;
            g_degs[idx] = dg;
            g_norm[idx] = rsqrtf(dg);
        }
    }
    if (t == SCAN_T - 1) g_rowptr[NN] = run;
}

__global__ void k_scatter(const int* __restrict__ src, const int* __restrict__ dst,
                          const int* __restrict__ efeat) {
    int e = blockIdx.x * blockDim.x + threadIdx.x;
    if (e < NE) {
        int d = dst[e];
        int pos = atomicAdd(&g_cursor[d], 1);
        g_edata[pos] = make_int2(src[e], efeat[e]);
    }
}

// h = nfeat @ W^T + b  -> g_h only.
// 256 threads = 16(tx) x 16(ty); 64 nodes x 128 outs; 4x8 regs/thread.
__global__ void k_gemm(const float* __restrict__ nfeat, const float* __restrict__ bias) {
    __shared__ float sA[BM][DD];
    __shared__ float sW[32][DD];

    int tid = threadIdx.x;
    int tx = tid & 15;
    int ty = tid >> 4;
    int m0 = blockIdx.x * BM;

    {
        const float4* nf4 = (const float4*)nfeat;
        float4* sA4 = (float4*)&sA[0][0];
        for (int t = tid; t < BM * DD / 4; t += 256) {
            int row = t >> 5;
            int n = m0 + row;
            float4 v = make_float4(0.f, 0.f, 0.f, 0.f);
            if (n < NN) v = nf4[n * 32 + (t & 31)];
            sA4[t] = v;
        }
    }

    float acc[4][8];
    #pragma unroll
    for (int i = 0; i < 4; i++)
        #pragma unroll
        for (int j = 0; j < 8; j++) acc[i][j] = 0.f;

    for (int k0 = 0; k0 < DD; k0 += 32) {
        __syncthreads();
        {
            const float4* w4 = (const float4*)(g_Wt + k0 * DD);
            float4* sW4 = (float4*)&sW[0][0];
            for (int t = tid; t < 32 * DD / 4; t += 256) sW4[t] = w4[t];
        }
        __syncthreads();

        #pragma unroll
        for (int kk = 0; kk < 32; kk++) {
            float a[4], w[8];
            #pragma unroll
            for (int i = 0; i < 4; i++) a[i] = sA[ty * 4 + i][k0 + kk];
            #pragma unroll
            for (int j = 0; j < 8; j++) w[j] = sW[kk][tx + 16 * j];
            #pragma unroll
            for (int i = 0; i < 4; i++)
                #pragma unroll
                for (int j = 0; j < 8; j++)
                    acc[i][j] = fmaf(a[i], w[j], acc[i][j]);
        }
    }

    #pragma unroll
    for (int i = 0; i < 4; i++) {
        int n = m0 + ty * 4 + i;
        if (n >= NN) continue;
        #pragma unroll
        for (int j = 0; j < 8; j++) {
            int d = tx + 16 * j;
            g_h[n * DD + d] = acc[i][j] + bias[d];
        }
    }
}

// Warp per node: accumulate incoming messages in registers, add residual, store.
// out[n] = n_dst * SUM_e n_src*relu(h[src]+emb[et]) + n_dst^2 * relu(h[n]+res_w)
__global__ void k_agg(const float* __restrict__ eemb, const float* __restrict__ res_w,
                      float* __restrict__ out) {
    int n = (blockIdx.x * blockDim.x + threadIdx.x) >> 5;
    if (n >= NN) return;
    int lane = threadIdx.x & 31;

    int rp0 = g_rowptr[n];
    int rp1 = g_rowptr[n + 1];

    float4 acc = make_float4(0.f, 0.f, 0.f, 0.f);
    for (int i = rp0; i < rp1; i++) {
        int2 se = g_edata[i];                    // broadcast
        float ns = g_norm[se.x];                 // broadcast
        float4 hv = ((const float4*)(g_h + se.x * DD))[lane];
        float4 ev = ((const float4*)(eemb + se.y * DD))[lane];
        acc.x += ns * fmaxf(hv.x + ev.x, 0.f);
        acc.y += ns * fmaxf(hv.y + ev.y, 0.f);
        acc.z += ns * fmaxf(hv.z + ev.z, 0.f);
        acc.w += ns * fmaxf(hv.w + ev.w, 0.f);
    }

    float nd = g_norm[n];
    float invd = nd * nd;                        // 1/degs
    float4 h  = ((const float4*)(g_h + n * DD))[lane];
    float4 rw = ((const float4*)res_w)[lane];
    float4 o;
    o.x = nd * acc.x + invd * fmaxf(h.x + rw.x, 0.f);
    o.y = nd * acc.y + invd * fmaxf(h.y + rw.y, 0.f);
    o.z = nd * acc.z + invd * fmaxf(h.z + rw.z, 0.f);
    o.w = nd * acc.w + invd * fmaxf(h.w + rw.w, 0.f);
    ((float4*)(out + n * DD))[lane] = o;
}

extern "C" void kernel_launch(void* const* d_in, const int* in_sizes, int n_in,
                              void* d_out, int out_size) {
    const float* nfeat = (const float*)d_in[0];
    const int*   efeat = (const int*)d_in[1];
    const int*   src   = (const int*)d_in[2];
    const int*   dst   = (const int*)d_in[3];
    const float* W     = (const float*)d_in[4];
    const float* bias  = (const float*)d_in[5];
    const float* eemb  = (const float*)d_in[6];
    const float* res_w = (const float*)d_in[7];
    float* out = (float*)d_out;

    k_pre<<<(NN + 255) / 256, 256>>>(W);
    k_count<<<(NE + 255) / 256, 256>>>(dst);
    k_scan<<<1, SCAN_T>>>();
    k_scatter<<<(NE + 255) / 256, 256>>>(src, dst, efeat);
    k_gemm<<<(NN + BM - 1) / BM, 256>>>(nfeat, bias);
    k_agg<<<(NN * 32 + 255) / 256, 256>>>(eemb, res_w, out);
}

// round 4
// speedup vs baseline: 1.9217x; 1.9217x over previous
#include <cuda_runtime.h>
#include <cuda_fp16.h>

#define NN 50000
#define NE 800000
#define DD 128
#define BM 64
#define NB 196          // ceil(NN/256) scan blocks

// Scratch (__device__ globals per allocation rules)
__device__ float  g_h[NN * DD];        // projected node features (fp32, residual path)
__device__ __half g_hh[NN * DD];       // fp16 copy for edge gathers
__device__ float  g_degs[NN];
__device__ float  g_norm[NN];
__device__ float  g_Wt[DD * DD];
__device__ int    g_cnt[NN];           // in-degree histogram
__device__ int    g_rowptr[NN + 1];
__device__ int    g_cursor[NN];
__device__ int    g_bsum[256];         // per-block counts (padded)
__device__ int    g_boff[256];         // per-block exclusive offsets
__device__ int    g_edata[NE];         // (src<<4)|etype, binned by dst

// Zero histogram + transpose W
__global__ void k_pre(const float* __restrict__ W) {
    int i = blockIdx.x * blockDim.x + threadIdx.x;
    if (i < NN) g_cnt[i] = 0;
    if (i < DD * DD) {
        int d = i >> 7, k = i & 127;
        g_Wt[k * DD + d] = W[i];
    }
}

__global__ void k_count(const int* __restrict__ dst) {
    int e = blockIdx.x * blockDim.x + threadIdx.x;
    if (e < NE) atomicAdd(&g_cnt[dst[e]], 1);
}

// Phase 1: per-block sums of cnt
__global__ void k_bsum() {
    __shared__ int s[256];
    int t = threadIdx.x;
    int idx = blockIdx.x * 256 + t;
    s[t] = (idx < NN) ? g_cnt[idx] : 0;
    __syncthreads();
    for (int off = 128; off > 0; off >>= 1) {
        if (t < off) s[t] += s[t + off];
        __syncthreads();
    }
    if (t == 0) g_bsum[blockIdx.x] = s[0];
}

// Phase 2: scan the 196 block sums (one block)
__global__ void k_boff() {
    __shared__ int s[256];
    int t = threadIdx.x;
    int v = (t < NB) ? g_bsum[t] : 0;
    s[t] = v;
    __syncthreads();
    for (int off = 1; off < 256; off <<= 1) {
        int u = (t >= off) ? s[t - off] : 0;
        __syncthreads();
        s[t] += u;
        __syncthreads();
    }
    if (t < NB) g_boff[t] = s[t] - v;           // exclusive
    if (t == NB - 1) g_rowptr[NN] = s[t];       // total
}

// Phase 3: in-block scan + write rowptr/cursor/degs/norm
__global__ void k_final() {
    __shared__ int s[256];
    int t = threadIdx.x;
    int idx = blockIdx.x * 256 + t;
    int v = (idx < NN) ? g_cnt[idx] : 0;
    s[t] = v;
    __syncthreads();
    for (int off = 1; off < 256; off <<= 1) {
        int u = (t >= off) ? s[t - off] : 0;
        __syncthreads();
        s[t] += u;
        __syncthreads();
    }
    if (idx < NN) {
        int rp = g_boff[blockIdx.x] + s[t] - v;  // exclusive prefix
        g_rowptr[idx] = rp;
        g_cursor[idx] = rp;
        float dg = (float)v + 1.0f;
        g_degs[idx] = dg;
        g_norm[idx] = rsqrtf(dg);
    }
}

// h = nfeat @ W^T + b  ->  g_h (fp32) + g_hh (fp16)
__global__ void k_gemm(const float* __restrict__ nfeat, const float* __restrict__ bias) {
    __shared__ float sA[BM][DD];
    __shared__ float sW[32][DD];

    int tid = threadIdx.x;
    int tx = tid & 15;
    int ty = tid >> 4;
    int m0 = blockIdx.x * BM;

    {
        const float4* nf4 = (const float4*)nfeat;
        float4* sA4 = (float4*)&sA[0][0];
        for (int t = tid; t < BM * DD / 4; t += 256) {
            int row = t >> 5;
            int n = m0 + row;
            float4 v = make_float4(0.f, 0.f, 0.f, 0.f);
            if (n < NN) v = nf4[n * 32 + (t & 31)];
            sA4[t] = v;
        }
    }

    float acc[4][8];
    #pragma unroll
    for (int i = 0; i < 4; i++)
        #pragma unroll
        for (int j = 0; j < 8; j++) acc[i][j] = 0.f;

    for (int k0 = 0; k0 < DD; k0 += 32) {
        __syncthreads();
        {
            const float4* w4 = (const float4*)(g_Wt + k0 * DD);
            float4* sW4 = (float4*)&sW[0][0];
            for (int t = tid; t < 32 * DD / 4; t += 256) sW4[t] = w4[t];
        }
        __syncthreads();

        #pragma unroll
        for (int kk = 0; kk < 32; kk++) {
            float a[4], w[8];
            #pragma unroll
            for (int i = 0; i < 4; i++) a[i] = sA[ty * 4 + i][k0 + kk];
            #pragma unroll
            for (int j = 0; j < 8; j++) w[j] = sW[kk][tx + 16 * j];
            #pragma unroll
            for (int i = 0; i < 4; i++)
                #pragma unroll
                for (int j = 0; j < 8; j++)
                    acc[i][j] = fmaf(a[i], w[j], acc[i][j]);
        }
    }

    #pragma unroll
    for (int i = 0; i < 4; i++) {
        int n = m0 + ty * 4 + i;
        if (n >= NN) continue;
        #pragma unroll
        for (int j = 0; j < 8; j++) {
            int d = tx + 16 * j;
            float h = acc[i][j] + bias[d];
            g_h[n * DD + d] = h;
            g_hh[n * DD + d] = __float2half_rn(h);
        }
    }
}

__global__ void k_scatter(const int* __restrict__ src, const int* __restrict__ dst,
                          const int* __restrict__ efeat) {
    int e = blockIdx.x * blockDim.x + threadIdx.x;
    if (e < NE) {
        int d = dst[e];
        int pos = atomicAdd(&g_cursor[d], 1);
        g_edata[pos] = (src[e] << 4) | efeat[e];
    }
}

// Warp per node: register-accumulated segment sum + residual, one plain store.
__global__ void k_agg(const float* __restrict__ eemb, const float* __restrict__ res_w,
                      float* __restrict__ out) {
    int n = (blockIdx.x * blockDim.x + threadIdx.x) >> 5;
    if (n >= NN) return;
    int lane = threadIdx.x & 31;

    int i   = g_rowptr[n];
    int end = g_rowptr[n + 1];

    float4 acc = make_float4(0.f, 0.f, 0.f, 0.f);
    int pn = (i < end) ? g_edata[i] : 0;        // prefetch edge 0
    while (i < end) {
        int p = pn;
        if (i + 1 < end) pn = g_edata[i + 1];   // prefetch next: gather addr ready early
        int s = p >> 4;
        int t = p & 15;
        float ns = g_norm[s];
        uint2 raw = ((const uint2*)(g_hh + s * DD))[lane];   // 4 halves / lane
        float2 f01 = __half22float2(*(__half2*)&raw.x);
        float2 f23 = __half22float2(*(__half2*)&raw.y);
        float4 ev = ((const float4*)(eemb + t * DD))[lane];
        acc.x += ns * fmaxf(f01.x + ev.x, 0.f);
        acc.y += ns * fmaxf(f01.y + ev.y, 0.f);
        acc.z += ns * fmaxf(f23.x + ev.z, 0.f);
        acc.w += ns * fmaxf(f23.y + ev.w, 0.f);
        i++;
    }

    float nd = g_norm[n];
    float invd = nd * nd;                        // 1/degs
    float4 h  = ((const float4*)(g_h + n * DD))[lane];
    float4 rw = ((const float4*)res_w)[lane];
    float4 o;
    o.x = nd * acc.x + invd * fmaxf(h.x + rw.x, 0.f);
    o.y = nd * acc.y + invd * fmaxf(h.y + rw.y, 0.f);
    o.z = nd * acc.z + invd * fmaxf(h.z + rw.z, 0.f);
    o.w = nd * acc.w + invd * fmaxf(h.w + rw.w, 0.f);
    ((float4*)(out + n * DD))[lane] = o;
}

extern "C" void kernel_launch(void* const* d_in, const int* in_sizes, int n_in,
                              void* d_out, int out_size) {
    const float* nfeat = (const float*)d_in[0];
    const int*   efeat = (const int*)d_in[1];
    const int*   src   = (const int*)d_in[2];
    const int*   dst   = (const int*)d_in[3];
    const float* W     = (const float*)d_in[4];
    const float* bias  = (const float*)d_in[5];
    const float* eemb  = (const float*)d_in[6];
    const float* res_w = (const float*)d_in[7];
    float* out = (float*)d_out;

    k_pre    <<<(NN + 255) / 256, 256>>>(W);      // launch 0
    k_count  <<<(NE + 255) / 256, 256>>>(dst);    // launch 1
    k_bsum   <<<NB, 256>>>();                     // launch 2
    k_boff   <<<1, 256>>>();                      // launch 3
    k_final  <<<NB, 256>>>();                     // launch 4
    k_gemm   <<<(NN + BM - 1) / BM, 256>>>(nfeat, bias);   // launch 5 (profiled by -s 5)
    k_scatter<<<(NE + 255) / 256, 256>>>(src, dst, efeat); // launch 6
    k_agg    <<<(NN * 32 + 255) / 256, 256>>>(eemb, res_w, out); // launch 7
}

// round 6
// speedup vs baseline: 1.9497x; 1.0146x over previous
#include <cuda_runtime.h>
#include <cuda_fp16.h>
#include <cstdint>

#define NN 50000
#define NE 800000
#define DD 128
#define NB 196          // ceil(NN/256) scan blocks
#define BM 64
#define GEMM_BLOCKS ((NN + BM - 1) / BM)   // 782

// Scratch (__device__ globals per allocation rules)
__device__ __half g_hh[NN * DD];       // projected node features (fp16)
__device__ __half g_eh[16 * DD];       // edge-type embeddings (fp16)
__device__ float  g_norm[NN];
__device__ float  g_Wt[DD * DD];       // W transposed
__device__ int    g_cnt[NN];
__device__ int    g_rowptr[NN + 1];
__device__ int    g_cursor[NN];
__device__ int    g_bsum[256];
__device__ int    g_boff[256];
__device__ int    g_edata[NE];         // (src<<4)|etype, binned by dst

// ---------------- CSR chain (stream 1) ----------------
__global__ void k_pre(const float* __restrict__ eemb) {
    int i = blockIdx.x * blockDim.x + threadIdx.x;
    if (i < NN) g_cnt[i] = 0;
    if (i < 16 * DD) g_eh[i] = __float2half_rn(eemb[i]);
}

__global__ void k_count(const int* __restrict__ dst) {
    int e = blockIdx.x * blockDim.x + threadIdx.x;
    if (e < NE) atomicAdd(&g_cnt[dst[e]], 1);
}

__global__ void k_bsum() {
    __shared__ int s[256];
    int t = threadIdx.x;
    int idx = blockIdx.x * 256 + t;
    s[t] = (idx < NN) ? g_cnt[idx] : 0;
    __syncthreads();
    for (int off = 128; off > 0; off >>= 1) {
        if (t < off) s[t] += s[t + off];
        __syncthreads();
    }
    if (t == 0) g_bsum[blockIdx.x] = s[0];
}

__global__ void k_boff() {
    __shared__ int s[256];
    int t = threadIdx.x;
    int v = (t < NB) ? g_bsum[t] : 0;
    s[t] = v;
    __syncthreads();
    for (int off = 1; off < 256; off <<= 1) {
        int u = (t >= off) ? s[t - off] : 0;
        __syncthreads();
        s[t] += u;
        __syncthreads();
    }
    if (t < NB) g_boff[t] = s[t] - v;
    if (t == NB - 1) g_rowptr[NN] = s[t];
}

__global__ void k_final() {
    __shared__ int s[256];
    int t = threadIdx.x;
    int idx = blockIdx.x * 256 + t;
    int v = (idx < NN) ? g_cnt[idx] : 0;
    s[t] = v;
    __syncthreads();
    for (int off = 1; off < 256; off <<= 1) {
        int u = (t >= off) ? s[t - off] : 0;
        __syncthreads();
        s[t] += u;
        __syncthreads();
    }
    if (idx < NN) {
        int rp = g_boff[blockIdx.x] + s[t] - v;
        g_rowptr[idx] = rp;
        g_cursor[idx] = rp;
        g_norm[idx] = rsqrtf((float)v + 1.0f);
    }
}

__global__ void k_scatter(const int* __restrict__ src, const int* __restrict__ dst,
                          const int* __restrict__ efeat) {
    int e = blockIdx.x * blockDim.x + threadIdx.x;
    if (e < NE) {
        int d = dst[e];
        int pos = atomicAdd(&g_cursor[d], 1);
        g_edata[pos] = (src[e] << 4) | efeat[e];
    }
}

// ---------------- GEMM chain (stream 0) ----------------
__global__ void k_transpose(const float* __restrict__ W) {
    int i = blockIdx.x * blockDim.x + threadIdx.x;   // i = d*128 + k
    if (i < DD * DD) {
        int d = i >> 7, k = i & 127;
        g_Wt[k * DD + d] = W[i];
    }
}

// h = nfeat @ W^T + b -> g_hh (fp16).
// Tile: 64 nodes x 128 outs, full K=128 resident.
// Thread (tx,ty): tx=tid&15 owns d = tx*8..tx*8+7 ; ty=tid>>4 owns nodes ty*4..+3.
#define SWT_PITCH 132
#define SA_BYTES (BM * DD * 4)                    // 32768
#define SWT_BYTES (DD * SWT_PITCH * 4)            // 67584
#define GEMM_SMEM (SA_BYTES + SWT_BYTES)          // 100352

__global__ void __launch_bounds__(256, 2)
k_gemm(const float* __restrict__ nfeat, const float* __restrict__ bias) {
    extern __shared__ float sm[];
    float* sA  = sm;                      // [64][128]
    float* sWt = sm + BM * DD;            // [128][132]

    int tid = threadIdx.x;
    int tx = tid & 15;
    int ty = tid >> 4;
    int m0 = blockIdx.x * BM;

    // Fill sWt from g_Wt (coalesced read, conflict-free store)
    {
        const float4* wt4 = (const float4*)g_Wt;
        for (int idx = tid; idx < DD * 32; idx += 256) {
            int k = idx >> 5, q = idx & 31;
            *(float4*)(sWt + k * SWT_PITCH + q * 4) = wt4[idx];
        }
    }
    // Fill sA (zero-pad past NN)
    {
        const float4* nf4 = (const float4*)nfeat;
        for (int t = tid; t < BM * 32; t += 256) {
            int row = t >> 5, q = t & 31;
            int n = m0 + row;
            float4 v = make_float4(0.f, 0.f, 0.f, 0.f);
            if (n < NN) v = nf4[n * 32 + q];
            *(float4*)(sA + row * DD + q * 4) = v;
        }
    }
    __syncthreads();

    float acc[4][8];
    #pragma unroll
    for (int i = 0; i < 4; i++)
        #pragma unroll
        for (int j = 0; j < 8; j++) acc[i][j] = 0.f;

    #pragma unroll 4
    for (int kk = 0; kk < DD; kk++) {
        float4 w0 = *(const float4*)(sWt + kk * SWT_PITCH + tx * 8);
        float4 w1 = *(const float4*)(sWt + kk * SWT_PITCH + tx * 8 + 4);
        float a0 = sA[(ty * 4 + 0) * DD + kk];
        float a1 = sA[(ty * 4 + 1) * DD + kk];
        float a2 = sA[(ty * 4 + 2) * DD + kk];
        float a3 = sA[(ty * 4 + 3) * DD + kk];
        float w[8] = {w0.x, w0.y, w0.z, w0.w, w1.x, w1.y, w1.z, w1.w};
        float a[4] = {a0, a1, a2, a3};
        #pragma unroll
        for (int i = 0; i < 4; i++)
            #pragma unroll
            for (int j = 0; j < 8; j++)
                acc[i][j] = fmaf(a[i], w[j], acc[i][j]);
    }

    // Epilogue: +bias, convert fp16, vector store (16B per node per thread)
    float4 b0 = ((const float4*)bias)[tx * 2];
    float4 b1 = ((const float4*)bias)[tx * 2 + 1];
    #pragma unroll
    for (int i = 0; i < 4; i++) {
        int n = m0 + ty * 4 + i;
        if (n >= NN) continue;
        __half2 h0 = __floats2half2_rn(acc[i][0] + b0.x, acc[i][1] + b0.y);
        __half2 h1 = __floats2half2_rn(acc[i][2] + b0.z, acc[i][3] + b0.w);
        __half2 h2 = __floats2half2_rn(acc[i][4] + b1.x, acc[i][5] + b1.y);
        __half2 h3 = __floats2half2_rn(acc[i][6] + b1.z, acc[i][7] + b1.w);
        uint4 pk = make_uint4(*(uint32_t*)&h0, *(uint32_t*)&h1,
                              *(uint32_t*)&h2, *(uint32_t*)&h3);
        *(uint4*)(g_hh + n * DD + tx * 8) = pk;
    }
}

// ---------------- aggregation (after join) ----------------
__global__ void k_agg(const float* __restrict__ res_w, float* __restrict__ out) {
    int n = (blockIdx.x * blockDim.x + threadIdx.x) >> 5;
    if (n >= NN) return;
    int lane = threadIdx.x & 31;

    int i   = g_rowptr[n];
    int end = g_rowptr[n + 1];

    float4 acc = make_float4(0.f, 0.f, 0.f, 0.f);
    if (i < end) {
        int p = g_edata[i];
        int s = p >> 4, t = p & 15;
        float ns = g_norm[s];
        uint2 rh = ((const uint2*)(g_hh + s * DD))[lane];
        uint2 re = ((const uint2*)(g_eh + t * DD))[lane];
        for (++i; i < end; ++i) {
            int p2 = g_edata[i];
            int s2 = p2 >> 4, t2 = p2 & 15;
            float ns2 = g_norm[s2];
            uint2 rh2 = ((const uint2*)(g_hh + s2 * DD))[lane];
            uint2 re2 = ((const uint2*)(g_eh + t2 * DD))[lane];
            float2 f01 = __half22float2(*(__half2*)&rh.x);
            float2 f23 = __half22float2(*(__half2*)&rh.y);
            float2 e01 = __half22float2(*(__half2*)&re.x);
            float2 e23 = __half22float2(*(__half2*)&re.y);
            acc.x += ns * fmaxf(f01.x + e01.x, 0.f);
            acc.y += ns * fmaxf(f01.y + e01.y, 0.f);
            acc.z += ns * fmaxf(f23.x + e23.x, 0.f);
            acc.w += ns * fmaxf(f23.y + e23.y, 0.f);
            rh = rh2; re = re2; ns = ns2;
        }
        float2 f01 = __half22float2(*(__half2*)&rh.x);
        float2 f23 = __half22float2(*(__half2*)&rh.y);
        float2 e01 = __half22float2(*(__half2*)&re.x);
        float2 e23 = __half22float2(*(__half2*)&re.y);
        acc.x += ns * fmaxf(f01.x + e01.x, 0.f);
        acc.y += ns * fmaxf(f01.y + e01.y, 0.f);
        acc.z += ns * fmaxf(f23.x + e23.x, 0.f);
        acc.w += ns * fmaxf(f23.y + e23.y, 0.f);
    }

    float nd = g_norm[n];
    float invd = nd * nd;
    uint2 rh = ((const uint2*)(g_hh + n * DD))[lane];
    float2 h01 = __half22float2(*(__half2*)&rh.x);
    float2 h23 = __half22float2(*(__half2*)&rh.y);
    float4 rw = ((const float4*)res_w)[lane];
    float4 o;
    o.x = nd * acc.x + invd * fmaxf(h01.x + rw.x, 0.f);
    o.y = nd * acc.y + invd * fmaxf(h01.y + rw.y, 0.f);
    o.z = nd * acc.z + invd * fmaxf(h23.x + rw.z, 0.f);
    o.w = nd * acc.w + invd * fmaxf(h23.y + rw.w, 0.f);
    ((float4*)(out + n * DD))[lane] = o;
}

extern "C" void kernel_launch(void* const* d_in, const int* in_sizes, int n_in,
                              void* d_out, int out_size) {
    const float* nfeat = (const float*)d_in[0];
    const int*   efeat = (const int*)d_in[1];
    const int*   src   = (const int*)d_in[2];
    const int*   dst   = (const int*)d_in[3];
    const float* W     = (const float*)d_in[4];
    const float* bias  = (const float*)d_in[5];
    const float* eemb  = (const float*)d_in[6];
    const float* res_w = (const float*)d_in[7];
    float* out = (float*)d_out;

    static cudaStream_t s1 = nullptr;
    static cudaEvent_t evF = nullptr, evJ = nullptr;
    if (!s1) {
        cudaStreamCreateWithFlags(&s1, cudaStreamNonBlocking);
        cudaEventCreateWithFlags(&evF, cudaEventDisableTiming);
        cudaEventCreateWithFlags(&evJ, cudaEventDisableTiming);
        cudaFuncSetAttribute(k_gemm, cudaFuncAttributeMaxDynamicSharedMemorySize, GEMM_SMEM);
    }

    // Fork: CSR chain on s1
    cudaEventRecord(evF, 0);
    cudaStreamWaitEvent(s1, evF, 0);
    k_pre    <<<(NN + 255) / 256, 256, 0, s1>>>(eemb);
    k_count  <<<(NE + 255) / 256, 256, 0, s1>>>(dst);
    k_bsum   <<<NB, 256, 0, s1>>>();
    k_boff   <<<1, 256, 0, s1>>>();
    k_final  <<<NB, 256, 0, s1>>>();
    k_scatter<<<(NE + 255) / 256, 256, 0, s1>>>(src, dst, efeat);
    cudaEventRecord(evJ, s1);

    // GEMM chain on stream 0 (concurrent)
    k_transpose<<<(DD * DD + 255) / 256, 256>>>(W);
    k_gemm<<<GEMM_BLOCKS, 256, GEMM_SMEM>>>(nfeat, bias);

    // Join, then aggregate
    cudaStreamWaitEvent(0, evJ, 0);
    k_agg<<<(NN * 32 + 255) / 256, 256>>>(res_w, out);
}

// round 7
// speedup vs baseline: 2.0209x; 1.0365x over previous
#include <cuda_runtime.h>
#include <cuda_fp16.h>
#include <cstdint>

#define NN 50000
#define NE 800000
#define DD 128
#define NB 196          // ceil(NN/256) scan blocks
#define BM 64
#define GEMM_BLOCKS ((NN + BM - 1) / BM)   // 782

// Scratch (__device__ globals per allocation rules; zero-initialized at load)
__device__ __half g_hh[NN * DD];       // projected node features (fp16)
__device__ __half g_eh[16 * DD];       // edge-type embeddings (fp16)
__device__ float  g_norm[NN];
__device__ int    g_cnt[NN];           // in-degree histogram (re-zeroed by k_final)
__device__ int    g_rowptr[NN + 1];
__device__ int    g_cursor[NN];
__device__ int    g_bsum[256];
__device__ int    g_boff[256];
__device__ int    g_done;              // last-block flag (re-zeroed each use)
__device__ int    g_edata[NE];         // (src<<4)|etype, binned by dst

// ---------------- CSR chain (stream sB) ----------------
// count in-degrees; also convert eemb -> fp16 (independent side job)
__global__ void k_count(const int* __restrict__ dst, const float* __restrict__ eemb) {
    int e = blockIdx.x * blockDim.x + threadIdx.x;
    if (e < 16 * DD) g_eh[e] = __float2half_rn(eemb[e]);
    if (e < NE) atomicAdd(&g_cnt[dst[e]], 1);
}

// per-block sums + last block scans them (fused bsum+boff)
__global__ void k_bsumboff() {
    __shared__ int s[256];
    __shared__ int isLast;
    int t = threadIdx.x;
    int idx = blockIdx.x * 256 + t;
    int v = (idx < NN) ? g_cnt[idx] : 0;
    s[t] = v;
    __syncthreads();
    for (int off = 128; off > 0; off >>= 1) {
        if (t < off) s[t] += s[t + off];
        __syncthreads();
    }
    if (t == 0) {
        g_bsum[blockIdx.x] = s[0];
        __threadfence();
        int d = atomicAdd(&g_done, 1);
        isLast = (d == (int)gridDim.x - 1);
    }
    __syncthreads();
    if (isLast) {
        int v2 = (t < NB) ? *((volatile int*)&g_bsum[t]) : 0;
        s[t] = v2;
        __syncthreads();
        for (int off = 1; off < 256; off <<= 1) {
            int u = (t >= off) ? s[t - off] : 0;
            __syncthreads();
            s[t] += u;
            __syncthreads();
        }
        if (t < NB) g_boff[t] = s[t] - v2;
        if (t == NB - 1) g_rowptr[NN] = s[t];
        if (t == 0) g_done = 0;
    }
}

// in-block scan -> rowptr/cursor/norm ; re-zero g_cnt for the next replay
__global__ void k_final() {
    __shared__ int s[256];
    int t = threadIdx.x;
    int idx = blockIdx.x * 256 + t;
    int v = (idx < NN) ? g_cnt[idx] : 0;
    s[t] = v;
    __syncthreads();
    for (int off = 1; off < 256; off <<= 1) {
        int u = (t >= off) ? s[t - off] : 0;
        __syncthreads();
        s[t] += u;
        __syncthreads();
    }
    if (idx < NN) {
        int rp = g_boff[blockIdx.x] + s[t] - v;
        g_rowptr[idx] = rp;
        g_cursor[idx] = rp;
        g_norm[idx] = rsqrtf((float)v + 1.0f);
        g_cnt[idx] = 0;                   // restore invariant for next replay
    }
}

__global__ void k_scatter(const int* __restrict__ src, const int* __restrict__ dst,
                          const int* __restrict__ efeat) {
    int e = blockIdx.x * blockDim.x + threadIdx.x;
    if (e < NE) {
        int d = dst[e];
        int pos = atomicAdd(&g_cursor[d], 1);
        g_edata[pos] = (src[e] << 4) | efeat[e];
    }
}

// ---------------- GEMM chain (stream sA) ----------------
// h = nfeat @ W^T + b -> g_hh (fp16). W transposed global->smem inline.
#define SWT_PITCH 132
#define SA_BYTES (BM * DD * 4)                    // 32768
#define SWT_BYTES (DD * SWT_PITCH * 4)            // 67584
#define GEMM_SMEM (SA_BYTES + SWT_BYTES)          // 100352

__global__ void __launch_bounds__(256, 2)
k_gemm(const float* __restrict__ nfeat, const float* __restrict__ W,
       const float* __restrict__ bias) {
    extern __shared__ float sm[];
    float* sA  = sm;                      // [64][128]
    float* sWt = sm + BM * DD;            // [128][132]  (sWt[k][d])

    int tid = threadIdx.x;
    int tx = tid & 15;
    int ty = tid >> 4;
    int m0 = blockIdx.x * BM;

    // Inline transpose: W[d][k] (coalesced read) -> sWt[k][d]
    for (int i = tid; i < DD * DD; i += 256) {
        int d = i >> 7, k = i & 127;
        sWt[k * SWT_PITCH + d] = W[i];
    }
    // Node-feature tile
    {
        const float4* nf4 = (const float4*)nfeat;
        for (int t = tid; t < BM * 32; t += 256) {
            int row = t >> 5, q = t & 31;
            int n = m0 + row;
            float4 v = make_float4(0.f, 0.f, 0.f, 0.f);
            if (n < NN) v = nf4[n * 32 + q];
            *(float4*)(sA + row * DD + q * 4) = v;
        }
    }
    __syncthreads();

    float acc[4][8];
    #pragma unroll
    for (int i = 0; i < 4; i++)
        #pragma unroll
        for (int j = 0; j < 8; j++) acc[i][j] = 0.f;

    #pragma unroll 4
    for (int kk = 0; kk < DD; kk++) {
        float4 w0 = *(const float4*)(sWt + kk * SWT_PITCH + tx * 8);
        float4 w1 = *(const float4*)(sWt + kk * SWT_PITCH + tx * 8 + 4);
        float a[4];
        #pragma unroll
        for (int i = 0; i < 4; i++) a[i] = sA[(ty * 4 + i) * DD + kk];
        float w[8] = {w0.x, w0.y, w0.z, w0.w, w1.x, w1.y, w1.z, w1.w};
        #pragma unroll
        for (int i = 0; i < 4; i++)
            #pragma unroll
            for (int j = 0; j < 8; j++)
                acc[i][j] = fmaf(a[i], w[j], acc[i][j]);
    }

    float4 b0 = ((const float4*)bias)[tx * 2];
    float4 b1 = ((const float4*)bias)[tx * 2 + 1];
    #pragma unroll
    for (int i = 0; i < 4; i++) {
        int n = m0 + ty * 4 + i;
        if (n >= NN) continue;
        __half2 h0 = __floats2half2_rn(acc[i][0] + b0.x, acc[i][1] + b0.y);
        __half2 h1 = __floats2half2_rn(acc[i][2] + b0.z, acc[i][3] + b0.w);
        __half2 h2 = __floats2half2_rn(acc[i][4] + b1.x, acc[i][5] + b1.y);
        __half2 h3 = __floats2half2_rn(acc[i][6] + b1.z, acc[i][7] + b1.w);
        uint4 pk = make_uint4(*(uint32_t*)&h0, *(uint32_t*)&h1,
                              *(uint32_t*)&h2, *(uint32_t*)&h3);
        *(uint4*)(g_hh + n * DD + tx * 8) = pk;
    }
}

// ---------------- aggregation (after join) ----------------
__global__ void __launch_bounds__(512, 4)
k_agg(const float* __restrict__ res_w, float* __restrict__ out) {
    __shared__ __half sE[16 * DD];       // 4KB edge-type table
    int tid = threadIdx.x;
    for (int i = tid; i < 16 * DD / 2; i += 512)
        ((uint32_t*)sE)[i] = ((const uint32_t*)g_eh)[i];
    __syncthreads();

    int n = (blockIdx.x * 512 + tid) >> 5;
    if (n >= NN) return;
    int lane = tid & 31;

    int i   = g_rowptr[n];
    int end = g_rowptr[n + 1];

    float4 acc = make_float4(0.f, 0.f, 0.f, 0.f);
    if (i < end) {
        int p = g_edata[i];
        int s = p >> 4, t = p & 15;
        float ns = g_norm[s];
        uint2 rh = ((const uint2*)(g_hh + s * DD))[lane];
        uint2 re = ((const uint2*)(sE + t * DD))[lane];
        for (++i; i < end; ++i) {
            int p2 = g_edata[i];
            int s2 = p2 >> 4, t2 = p2 & 15;
            float ns2 = g_norm[s2];
            uint2 rh2 = ((const uint2*)(g_hh + s2 * DD))[lane];
            uint2 re2 = ((const uint2*)(sE + t2 * DD))[lane];
            float2 f01 = __half22float2(*(__half2*)&rh.x);
            float2 f23 = __half22float2(*(__half2*)&rh.y);
            float2 e01 = __half22float2(*(__half2*)&re.x);
            float2 e23 = __half22float2(*(__half2*)&re.y);
            acc.x += ns * fmaxf(f01.x + e01.x, 0.f);
            acc.y += ns * fmaxf(f01.y + e01.y, 0.f);
            acc.z += ns * fmaxf(f23.x + e23.x, 0.f);
            acc.w += ns * fmaxf(f23.y + e23.y, 0.f);
            rh = rh2; re = re2; ns = ns2;
        }
        float2 f01 = __half22float2(*(__half2*)&rh.x);
        float2 f23 = __half22float2(*(__half2*)&rh.y);
        float2 e01 = __half22float2(*(__half2*)&re.x);
        float2 e23 = __half22float2(*(__half2*)&re.y);
        acc.x += ns * fmaxf(f01.x + e01.x, 0.f);
        acc.y += ns * fmaxf(f01.y + e01.y, 0.f);
        acc.z += ns * fmaxf(f23.x + e23.x, 0.f);
        acc.w += ns * fmaxf(f23.y + e23.y, 0.f);
    }

    float nd = g_norm[n];
    float invd = nd * nd;
    uint2 rh = ((const uint2*)(g_hh + n * DD))[lane];
    float2 h01 = __half22float2(*(__half2*)&rh.x);
    float2 h23 = __half22float2(*(__half2*)&rh.y);
    float4 rw = ((const float4*)res_w)[lane];
    float4 o;
    o.x = nd * acc.x + invd * fmaxf(h01.x + rw.x, 0.f);
    o.y = nd * acc.y + invd * fmaxf(h01.y + rw.y, 0.f);
    o.z = nd * acc.z + invd * fmaxf(h23.x + rw.z, 0.f);
    o.w = nd * acc.w + invd * fmaxf(h23.y + rw.w, 0.f);
    ((float4*)(out + n * DD))[lane] = o;
}

extern "C" void kernel_launch(void* const* d_in, const int* in_sizes, int n_in,
                              void* d_out, int out_size) {
    const float* nfeat = (const float*)d_in[0];
    const int*   efeat = (const int*)d_in[1];
    const int*   src   = (const int*)d_in[2];
    const int*   dst   = (const int*)d_in[3];
    const float* W     = (const float*)d_in[4];
    const float* bias  = (const float*)d_in[5];
    const float* eemb  = (const float*)d_in[6];
    const float* res_w = (const float*)d_in[7];
    float* out = (float*)d_out;

    static cudaStream_t sA = nullptr, sB = nullptr;
    static cudaEvent_t evF = nullptr, evA = nullptr, evB = nullptr;
    if (!sA) {
        cudaStreamCreateWithFlags(&sA, cudaStreamNonBlocking);
        cudaStreamCreateWithFlags(&sB, cudaStreamNonBlocking);
        cudaEventCreateWithFlags(&evF, cudaEventDisableTiming);
        cudaEventCreateWithFlags(&evA, cudaEventDisableTiming);
        cudaEventCreateWithFlags(&evB, cudaEventDisableTiming);
        cudaFuncSetAttribute(k_gemm, cudaFuncAttributeMaxDynamicSharedMemorySize, GEMM_SMEM);
    }

    // Fork from the caller's stream; BOTH chains run on created streams so the
    // legacy stream's implicit-sync semantics can't serialize them.
    cudaEventRecord(evF, 0);
    cudaStreamWaitEvent(sA, evF, 0);
    cudaStreamWaitEvent(sB, evF, 0);

    // CSR chain on sB
    k_count   <<<(NE + 255) / 256, 256, 0, sB>>>(dst, eemb);
    k_bsumboff<<<NB, 256, 0, sB>>>();
    k_final   <<<NB, 256, 0, sB>>>();
    k_scatter <<<(NE + 255) / 256, 256, 0, sB>>>(src, dst, efeat);
    cudaEventRecord(evB, sB);

    // GEMM chain on sA
    k_gemm<<<GEMM_BLOCKS, 256, GEMM_SMEM, sA>>>(nfeat, W, bias);
    cudaEventRecord(evA, sA);

    // Join, then aggregate on the caller's stream
    cudaStreamWaitEvent(0, evA, 0);
    cudaStreamWaitEvent(0, evB, 0);
    k_agg<<<(NN * 32 + 511) / 512, 512>>>(res_w, out);
}